// round 7
// baseline (speedup 1.0000x reference)
#include <cuda_runtime.h>
#include <cuda_bf16.h>

// Problem constants (fixed for RoIPointPool3d_23845658427905)
#define Bn 4
#define Nn 16384
#define Mn 128
#define Cn 128
#define Sn 512
#define ROW (3 + Cn)          // 131 floats per pooled row
#define NWORDS (Nn / 32)      // 512 ballot words per box
#define NT 512                // threads per block for kernel A
#define NWARP (NT / 32)       // 16

// kernel B tiling
#define RT 8                  // row-tiles per box
#define RS (Sn / RT)          // 64 output rows per tile
#define NTB 256               // threads per block for kernel B
#define NWARPB (NTB / 32)     // 8

// Scratch (device globals: allocation-free)
__device__ int g_table[Bn * Mn * Sn];   // per-box in-box point indices (first min(cnt,S))
__device__ int g_cnt[Bn * Mn];          // clamped in-box counts

// ---------------- Kernel A: box test + compaction ----------------
__global__ __launch_bounds__(NT, 3) void roipool_select_kernel(
    const float* __restrict__ points,   // (B, N, 3)
    const float* __restrict__ boxes,    // (B, M, 7)
    float* __restrict__ out,            // flags appended at end
    int write_flags)
{
    __shared__ unsigned s_words[NWORDS];
    __shared__ int s_warpSum[16];
    __shared__ int s_total;

    const int bm   = blockIdx.x;
    const int b    = bm >> 7;
    const int tid  = threadIdx.x;
    const int lane = tid & 31;
    const int wid  = tid >> 5;

    const float* box = boxes + bm * 7;
    const float cx = box[0];
    const float cy = box[1];
    const float dx = box[3], dy = box[4], dz = box[5];
    const float rz = box[6];
    const float cz = __fadd_rn(box[2], __fmul_rn(0.5f, dz));
    const float hx = __fmul_rn(0.5f, dx);
    const float hy = __fmul_rn(0.5f, dy);
    const float hz = __fmul_rn(0.5f, dz);
    const double nrz = -(double)rz;
    const float cosa = (float)cos(nrz);
    const float sina = (float)sin(nrz);

    const float* pts = points + (size_t)b * Nn * 3;

    // Phase 1: ballots (no block syncs, pipelined)
    #pragma unroll 4
    for (int W = wid; W < NWORDS; W += NWARP) {
        const int i = W * 32 + lane;
        const float px = pts[i * 3 + 0];
        const float py = pts[i * 3 + 1];
        const float pz = pts[i * 3 + 2];
        const float sx = __fsub_rn(px, cx);
        const float sy = __fsub_rn(py, cy);
        const float lx = __fsub_rn(__fmul_rn(sx, cosa), __fmul_rn(sy, sina));
        const float ly = __fadd_rn(__fmul_rn(sx, sina), __fmul_rn(sy, cosa));
        const bool in =
            (fabsf(__fsub_rn(pz, cz)) <= hz) &&
            (lx > -hx) && (lx < hx) &&
            (ly > -hy) && (ly < hy);
        const unsigned bal = __ballot_sync(0xffffffffu, in);
        if (lane == 0) s_words[W] = bal;
    }
    __syncthreads();

    // Phase 2: scan + ordered compaction, straight to global scratch
    unsigned w = s_words[tid];
    const int c = __popc(w);
    int incl = c;
    #pragma unroll
    for (int off = 1; off < 32; off <<= 1) {
        int v = __shfl_up_sync(0xffffffffu, incl, off);
        if (lane >= off) incl += v;
    }
    if (lane == 31) s_warpSum[wid] = incl;
    __syncthreads();
    if (wid == 0) {
        int v = (lane < 16) ? s_warpSum[lane] : 0;
        int iv = v;
        #pragma unroll
        for (int off = 1; off < 16; off <<= 1) {
            int t = __shfl_up_sync(0xffffffffu, iv, off);
            if (lane >= off) iv += t;
        }
        if (lane < 16) s_warpSum[lane] = iv - v;
        if (lane == 15) s_total = iv;
    }
    __syncthreads();

    int base = s_warpSum[wid] + (incl - c);
    const int word_pt = tid * 32;
    int* tbl = g_table + (size_t)bm * Sn;
    while (w) {
        const int bit = __ffs(w) - 1;
        w &= (w - 1);
        if (base < Sn) tbl[base] = word_pt + bit;
        base++;
    }

    if (tid == 0) {
        int cnt = s_total;
        if (cnt > Sn) cnt = Sn;
        g_cnt[bm] = cnt;
        if (write_flags)
            out[(size_t)Bn * Mn * Sn * ROW + bm] = (cnt == 0) ? 1.0f : 0.0f;
    }
}

// ---------------- Kernel B: tiled source-major replication ----------------
__global__ __launch_bounds__(NTB, 8) void roipool_write_kernel(
    const float* __restrict__ points,   // (B, N, 3)
    const float* __restrict__ feats,    // (B, N, C)
    float* __restrict__ out)            // (B, M, S, 131)
{
    const int bm   = blockIdx.x >> 3;       // / RT
    const int t    = blockIdx.x & (RT - 1);
    const int b    = bm >> 7;
    const int tid  = threadIdx.x;
    const int lane = tid & 31;
    const int wid  = tid >> 5;

    const int cnt = g_cnt[bm];
    const int r0 = t * RS;
    const int r1 = r0 + RS;
    float* outbox = out + (size_t)bm * Sn * ROW;

    if (cnt == 0) {
        // zero-fill the tile
        for (int r = r0 + wid; r < r1; r += NWARPB) {
            float* orow = outbox + (size_t)r * ROW;
            orow[lane]       = 0.f;
            orow[32 + lane]  = 0.f;
            orow[64 + lane]  = 0.f;
            orow[96 + lane]  = 0.f;
            if (lane < 3) orow[128 + lane] = 0.f;
        }
        return;
    }

    const float* pts = points + (size_t)b * Nn * 3;
    const float* fb  = feats  + (size_t)b * Nn * Cn;
    const int* tbl   = g_table + (size_t)bm * Sn;

    // source-major within the tile: output row r takes source (r % cnt)
    for (int j = wid; j < cnt; j += NWARPB) {
        // first replica >= r0 with r ≡ j (mod cnt)
        int r = (j >= r0) ? j : j + ((r0 - j + cnt - 1) / cnt) * cnt;
        if (r >= r1) continue;                    // no replica in this tile

        const int idx = tbl[j];
        const float* fr = fb + (size_t)idx * Cn;
        const float v0 = (lane < 3) ? pts[idx * 3 + lane] : fr[lane - 3];
        const float v1 = fr[32 + lane - 3];
        const float v2 = fr[64 + lane - 3];
        const float v3 = fr[96 + lane - 3];
        const float v4 = (lane < 3) ? fr[125 + lane] : 0.0f;

        for (; r < r1; r += cnt) {
            float* orow = outbox + (size_t)r * ROW;
            orow[lane]       = v0;
            orow[32 + lane]  = v1;
            orow[64 + lane]  = v2;
            orow[96 + lane]  = v3;
            if (lane < 3) orow[128 + lane] = v4;
        }
    }
}

extern "C" void kernel_launch(void* const* d_in, const int* in_sizes, int n_in,
                              void* d_out, int out_size)
{
    const float* points = (const float*)d_in[0];   // (B, N, 3)
    const float* feats  = (const float*)d_in[1];   // (B, N, C)
    const float* boxes  = (const float*)d_in[2];   // (B, M, 7)
    float* out = (float*)d_out;

    const long long pooled = (long long)Bn * Mn * Sn * ROW;   // 34,340,864
    const int write_flags = ((long long)out_size >= pooled + (long long)Bn * Mn) ? 1 : 0;

    roipool_select_kernel<<<Bn * Mn, NT>>>(points, boxes, out, write_flags);
    roipool_write_kernel<<<Bn * Mn * RT, NTB>>>(points, feats, out);
}

// round 8
// speedup vs baseline: 1.3780x; 1.3780x over previous
#include <cuda_runtime.h>
#include <cuda_bf16.h>

// Problem constants (fixed for RoIPointPool3d_23845658427905)
#define Bn 4
#define Nn 16384
#define Mn 128
#define Cn 128
#define Sn 512
#define ROW (3 + Cn)          // 131 floats per pooled row
#define NWORDS (Nn / 32)      // 512 ballot words per box

// Kernel A1 tiling: each CTA = 512 points x 32 boxes
#define PCH 512               // points per chunk
#define NCHUNK (Nn / PCH)     // 32
#define BG 32                 // boxes per CTA
#define NBG (Mn / BG)         // 4

// Kernel A2 / select
#define NT 512
#define NWARP (NT / 32)

// Kernel B tiling
#define RT 8                  // row-tiles per box
#define RS (Sn / RT)          // 64 output rows per tile
#define NTB 256
#define NWARPB (NTB / 32)

// Scratch (device globals: allocation-free)
__device__ float    g_boxp[Bn * Mn * 8];          // cx,cy,cz,hx,hy,hz,cosa,sina
__device__ unsigned g_words[Bn * Mn * NWORDS];    // in-box bitmasks (1 MB)
__device__ int      g_table[Bn * Mn * Sn];        // per-box compacted indices
__device__ int      g_cnt[Bn * Mn];               // clamped counts

// ---------------- A0: per-box parameter precompute ----------------
__global__ void roipool_params_kernel(const float* __restrict__ boxes)
{
    const int bm = threadIdx.x;                   // 512 threads, one per box
    const float* box = boxes + bm * 7;
    const float dz = box[5];
    float* p = g_boxp + bm * 8;
    p[0] = box[0];                                          // cx
    p[1] = box[1];                                          // cy
    p[2] = __fadd_rn(box[2], __fmul_rn(0.5f, dz));          // cz (geometric center)
    p[3] = __fmul_rn(0.5f, box[3]);                         // hx
    p[4] = __fmul_rn(0.5f, box[4]);                         // hy
    p[5] = __fmul_rn(0.5f, dz);                             // hz
    const double nrz = -(double)box[6];
    p[6] = (float)cos(nrz);                                 // cosa
    p[7] = (float)sin(nrz);                                 // sina
}

// ---------------- A1: point-in-box tests, points loaded once per 32 boxes ----
__global__ __launch_bounds__(512, 3) void roipool_test_kernel(
    const float* __restrict__ points)             // (B, N, 3)
{
    __shared__ float s_p[BG * 8];                 // box params for this group
    __shared__ unsigned s_bw[BG * 16];            // ballot words: [box][warp]

    const int cta   = blockIdx.x;
    const int bg    = cta & (NBG - 1);
    const int chunk = (cta >> 2) & (NCHUNK - 1);
    const int b     = cta >> 7;                   // / (NBG*NCHUNK) = /128
    const int tid   = threadIdx.x;
    const int lane  = tid & 31;
    const int wid   = tid >> 5;

    const int box_base = b * Mn + bg * BG;
    if (tid < BG * 8) s_p[tid] = g_boxp[box_base * 8 + tid];

    // each thread owns one point
    const int i = chunk * PCH + tid;
    const float* pp = points + ((size_t)b * Nn + i) * 3;
    const float px = pp[0];
    const float py = pp[1];
    const float pz = pp[2];
    __syncthreads();

    #pragma unroll 4
    for (int m = 0; m < BG; m++) {
        const float cx = s_p[m * 8 + 0];
        const float cy = s_p[m * 8 + 1];
        const float cz = s_p[m * 8 + 2];
        const float hx = s_p[m * 8 + 3];
        const float hy = s_p[m * 8 + 4];
        const float hz = s_p[m * 8 + 5];
        const float cosa = s_p[m * 8 + 6];
        const float sina = s_p[m * 8 + 7];
        const float sx = __fsub_rn(px, cx);
        const float sy = __fsub_rn(py, cy);
        const float lx = __fsub_rn(__fmul_rn(sx, cosa), __fmul_rn(sy, sina));
        const float ly = __fadd_rn(__fmul_rn(sx, sina), __fmul_rn(sy, cosa));
        const bool in =
            (fabsf(__fsub_rn(pz, cz)) <= hz) &&
            (lx > -hx) && (lx < hx) &&
            (ly > -hy) && (ly < hy);
        const unsigned bal = __ballot_sync(0xffffffffu, in);
        if (lane == 0) s_bw[m * 16 + wid] = bal;
    }
    __syncthreads();

    // coalesced write-out: tid -> (box m = tid/16, word w = tid%16)
    const int m = tid >> 4;
    const int w = tid & 15;
    g_words[(size_t)(box_base + m) * NWORDS + chunk * 16 + w] = s_bw[tid];
}

// ---------------- A2: scan + ordered compaction ----------------
__global__ __launch_bounds__(NT, 3) void roipool_scan_kernel(
    float* __restrict__ out, int write_flags)
{
    __shared__ int s_warpSum[16];
    __shared__ int s_total;

    const int bm   = blockIdx.x;
    const int tid  = threadIdx.x;
    const int lane = tid & 31;
    const int wid  = tid >> 5;

    unsigned w = g_words[(size_t)bm * NWORDS + tid];   // NWORDS == NT
    const int c = __popc(w);
    int incl = c;
    #pragma unroll
    for (int off = 1; off < 32; off <<= 1) {
        int v = __shfl_up_sync(0xffffffffu, incl, off);
        if (lane >= off) incl += v;
    }
    if (lane == 31) s_warpSum[wid] = incl;
    __syncthreads();
    if (wid == 0) {
        int v = (lane < 16) ? s_warpSum[lane] : 0;
        int iv = v;
        #pragma unroll
        for (int off = 1; off < 16; off <<= 1) {
            int t = __shfl_up_sync(0xffffffffu, iv, off);
            if (lane >= off) iv += t;
        }
        if (lane < 16) s_warpSum[lane] = iv - v;
        if (lane == 15) s_total = iv;
    }
    __syncthreads();

    int base = s_warpSum[wid] + (incl - c);
    const int word_pt = tid * 32;
    int* tbl = g_table + (size_t)bm * Sn;
    while (w) {
        const int bit = __ffs(w) - 1;
        w &= (w - 1);
        if (base < Sn) tbl[base] = word_pt + bit;
        base++;
    }

    if (tid == 0) {
        int cnt = s_total;
        if (cnt > Sn) cnt = Sn;
        g_cnt[bm] = cnt;
        if (write_flags)
            out[(size_t)Bn * Mn * Sn * ROW + bm] = (cnt == 0) ? 1.0f : 0.0f;
    }
}

// ---------------- B: tiled source-major replication ----------------
__global__ __launch_bounds__(NTB, 8) void roipool_write_kernel(
    const float* __restrict__ points,   // (B, N, 3)
    const float* __restrict__ feats,    // (B, N, C)
    float* __restrict__ out)            // (B, M, S, 131)
{
    const int bm   = blockIdx.x >> 3;       // / RT
    const int t    = blockIdx.x & (RT - 1);
    const int b    = bm >> 7;
    const int tid  = threadIdx.x;
    const int lane = tid & 31;
    const int wid  = tid >> 5;

    const int cnt = g_cnt[bm];
    const int r0 = t * RS;
    const int r1 = r0 + RS;
    float* outbox = out + (size_t)bm * Sn * ROW;

    if (cnt == 0) {
        for (int r = r0 + wid; r < r1; r += NWARPB) {
            float* orow = outbox + (size_t)r * ROW;
            __stcs(&orow[lane], 0.f);
            __stcs(&orow[32 + lane], 0.f);
            __stcs(&orow[64 + lane], 0.f);
            __stcs(&orow[96 + lane], 0.f);
            if (lane < 3) __stcs(&orow[128 + lane], 0.f);
        }
        return;
    }

    const float* pts = points + (size_t)b * Nn * 3;
    const float* fb  = feats  + (size_t)b * Nn * Cn;
    const int* tbl   = g_table + (size_t)bm * Sn;

    // source-major within the tile: output row r takes source (r % cnt)
    for (int j = wid; j < cnt; j += NWARPB) {
        int r = (j >= r0) ? j : j + ((r0 - j + cnt - 1) / cnt) * cnt;
        if (r >= r1) continue;

        const int idx = tbl[j];
        const float* fr = fb + (size_t)idx * Cn;
        const float v0 = (lane < 3) ? pts[idx * 3 + lane] : fr[lane - 3];
        const float v1 = fr[32 + lane - 3];
        const float v2 = fr[64 + lane - 3];
        const float v3 = fr[96 + lane - 3];
        const float v4 = (lane < 3) ? fr[125 + lane] : 0.0f;

        for (; r < r1; r += cnt) {
            float* orow = outbox + (size_t)r * ROW;
            __stcs(&orow[lane], v0);
            __stcs(&orow[32 + lane], v1);
            __stcs(&orow[64 + lane], v2);
            __stcs(&orow[96 + lane], v3);
            if (lane < 3) __stcs(&orow[128 + lane], v4);
        }
    }
}

extern "C" void kernel_launch(void* const* d_in, const int* in_sizes, int n_in,
                              void* d_out, int out_size)
{
    const float* points = (const float*)d_in[0];   // (B, N, 3)
    const float* feats  = (const float*)d_in[1];   // (B, N, C)
    const float* boxes  = (const float*)d_in[2];   // (B, M, 7)
    float* out = (float*)d_out;

    const long long pooled = (long long)Bn * Mn * Sn * ROW;   // 34,340,864
    const int write_flags = ((long long)out_size >= pooled + (long long)Bn * Mn) ? 1 : 0;

    roipool_params_kernel<<<1, Bn * Mn>>>(boxes);
    roipool_test_kernel<<<Bn * NCHUNK * NBG, 512>>>(points);
    roipool_scan_kernel<<<Bn * Mn, NT>>>(out, write_flags);
    roipool_write_kernel<<<Bn * Mn * RT, NTB>>>(points, feats, out);
}